// round 2
// baseline (speedup 1.0000x reference)
#include <cuda_runtime.h>
#include <cstdint>

#define BB 4
#define SS 2048
#define HH 16
#define DHD 64
#define DD 1024

// Scratch: Q/K/V in [B, H, S, DH] layout. Q is pre-scaled by 1/sqrt(DH).
__device__ float g_q[(size_t)BB * HH * SS * DHD];
__device__ float g_k[(size_t)BB * HH * SS * DHD];
__device__ float g_v[(size_t)BB * HH * SS * DHD];

__device__ __forceinline__ uint32_t f2tf(float f) {
    uint32_t u;
    asm("cvt.rna.tf32.f32 %0, %1;" : "=r"(u) : "f"(f));
    return u;
}

__device__ __forceinline__ void mma8(float& d0, float& d1, float& d2, float& d3,
                                     uint32_t a0, uint32_t a1, uint32_t a2, uint32_t a3,
                                     uint32_t b0, uint32_t b1) {
    asm volatile(
        "mma.sync.aligned.m16n8k8.row.col.f32.tf32.tf32.f32 "
        "{%0,%1,%2,%3}, {%4,%5,%6,%7}, {%8,%9}, {%0,%1,%2,%3};"
        : "+f"(d0), "+f"(d1), "+f"(d2), "+f"(d3)
        : "r"(a0), "r"(a1), "r"(a2), "r"(a3), "r"(b0), "r"(b1));
}

// ============================================================================
// Kernel 1: fused QKV projection GEMM (tf32 mma, fp32 accum)
// C[8192, 1024] = X[8192,1024] @ W[1024,1024] + bias, written to [B,H,S,DH]
// grid = (64 m-tiles, 24 n-tiles: 8 per matrix x 3 matrices), 256 threads.
// ============================================================================
__global__ __launch_bounds__(256) void qkv_gemm_kernel(
    const float* __restrict__ x,
    const float* __restrict__ Wq, const float* __restrict__ bq,
    const float* __restrict__ Wk, const float* __restrict__ bk,
    const float* __restrict__ Wv, const float* __restrict__ bv)
{
    __shared__ float Xs[128][36];   // [m][k], pad 36 for conflict-free frag loads
    __shared__ float Ws[32][132];   // [k][n], pad 132

    const int mt = blockIdx.x;
    const int nt = blockIdx.y;                 // 0..23
    const int mat = nt >> 3;                   // 0=Q, 1=K, 2=V
    const int n0 = (nt & 7) * 128;

    const float* W;
    const float* bias;
    float* outp;
    float scale;
    if (mat == 0)      { W = Wq; bias = bq; outp = g_q; scale = 0.125f; }
    else if (mat == 1) { W = Wk; bias = bk; outp = g_k; scale = 1.0f; }
    else               { W = Wv; bias = bv; outp = g_v; scale = 1.0f; }

    const int tid  = threadIdx.x;
    const int warp = tid >> 5;
    const int lane = tid & 31;
    const int g    = lane >> 2;
    const int tig  = lane & 3;
    const int wm   = (warp & 1) * 64;   // warp m-offset within 128
    const int wn   = (warp >> 1) * 32;  // warp n-offset within 128
    const int m0   = mt * 128;

    float acc[4][4][4];
    #pragma unroll
    for (int mi = 0; mi < 4; mi++)
        #pragma unroll
        for (int ni = 0; ni < 4; ni++)
            #pragma unroll
            for (int r = 0; r < 4; r++)
                acc[mi][ni][r] = 0.0f;

    for (int k0 = 0; k0 < DD; k0 += 32) {
        // Load X tile 128x32 (float4, coalesced)
        #pragma unroll
        for (int i = 0; i < 4; i++) {
            int idx = tid + i * 256;          // 0..1023
            int r = idx >> 3;                  // 0..127
            int c = (idx & 7) << 2;            // 0,4,..,28
            float4 v = *(const float4*)(x + (size_t)(m0 + r) * DD + k0 + c);
            *(float4*)&Xs[r][c] = v;
        }
        // Load W tile 32x128 (float4, coalesced)
        #pragma unroll
        for (int i = 0; i < 4; i++) {
            int idx = tid + i * 256;
            int r = idx >> 5;                  // 0..31
            int c = (idx & 31) << 2;           // 0..124
            float4 v = *(const float4*)(W + (size_t)(k0 + r) * DD + n0 + c);
            *(float4*)&Ws[r][c] = v;
        }
        __syncthreads();

        #pragma unroll
        for (int kk = 0; kk < 4; kk++) {
            const int k8 = kk * 8;
            uint32_t A[4][4];
            #pragma unroll
            for (int mi = 0; mi < 4; mi++) {
                int row = wm + mi * 16;
                A[mi][0] = f2tf(Xs[row + g][k8 + tig]);
                A[mi][1] = f2tf(Xs[row + g + 8][k8 + tig]);
                A[mi][2] = f2tf(Xs[row + g][k8 + tig + 4]);
                A[mi][3] = f2tf(Xs[row + g + 8][k8 + tig + 4]);
            }
            uint32_t Bf[4][2];
            #pragma unroll
            for (int ni = 0; ni < 4; ni++) {
                int col = wn + ni * 8 + g;
                Bf[ni][0] = f2tf(Ws[k8 + tig][col]);
                Bf[ni][1] = f2tf(Ws[k8 + tig + 4][col]);
            }
            #pragma unroll
            for (int mi = 0; mi < 4; mi++)
                #pragma unroll
                for (int ni = 0; ni < 4; ni++)
                    mma8(acc[mi][ni][0], acc[mi][ni][1], acc[mi][ni][2], acc[mi][ni][3],
                         A[mi][0], A[mi][1], A[mi][2], A[mi][3],
                         Bf[ni][0], Bf[ni][1]);
        }
        __syncthreads();
    }

    // Epilogue: add bias, scale, scatter to [B,H,S,DH]
    #pragma unroll
    for (int mi = 0; mi < 4; mi++) {
        #pragma unroll
        for (int ni = 0; ni < 4; ni++) {
            const int n = n0 + wn + ni * 8 + 2 * tig;   // even, dh<=62
            const int h = n >> 6;
            const int dh = n & 63;
            const float bv0 = bias[n];
            const float bv1 = bias[n + 1];
            const int mbase = m0 + wm + mi * 16;
            {
                int m = mbase + g;
                int b = m >> 11, s = m & 2047;
                float2 v;
                v.x = (acc[mi][ni][0] + bv0) * scale;
                v.y = (acc[mi][ni][1] + bv1) * scale;
                *(float2*)(outp + ((size_t)(b * HH + h) * SS + s) * DHD + dh) = v;
            }
            {
                int m = mbase + g + 8;
                int b = m >> 11, s = m & 2047;
                float2 v;
                v.x = (acc[mi][ni][2] + bv0) * scale;
                v.y = (acc[mi][ni][3] + bv1) * scale;
                *(float2*)(outp + ((size_t)(b * HH + h) * SS + s) * DHD + dh) = v;
            }
        }
    }
}

// ============================================================================
// Kernel 2: flash attention (tf32 mma, online softmax, fp32 accum)
// grid = (S/64 = 32, B*H = 64), 128 threads (4 warps x 16 q-rows each).
// ============================================================================
#define KSTRIDE 68   // padded row stride (floats) for 64-wide tiles

__global__ __launch_bounds__(128) void attn_kernel(float* __restrict__ out)
{
    extern __shared__ float sm[];
    float* Qs = sm;                      // 64 x 68
    float* Ks = sm + 64 * KSTRIDE;       // 64 x 68
    float* Vs = sm + 2 * 64 * KSTRIDE;   // 64 x 68
    float* Ps = sm + 3 * 64 * KSTRIDE;   // 4 warps x 16 x 68

    const int bh = blockIdx.y;           // 0..63  (b*16 + h)
    const int q0 = blockIdx.x * 64;

    const float* qb = g_q + (size_t)bh * SS * DHD;
    const float* kb = g_k + (size_t)bh * SS * DHD;
    const float* vb = g_v + (size_t)bh * SS * DHD;

    const int tid  = threadIdx.x;
    const int warp = tid >> 5;
    const int lane = tid & 31;
    const int g    = lane >> 2;
    const int tig  = lane & 3;
    const int wrow = warp * 16;

    // Load Q tile (64x64) to smem
    #pragma unroll
    for (int i = 0; i < 8; i++) {
        int idx = tid + i * 128;       // 0..1023
        int r = idx >> 4;              // 0..63
        int c = (idx & 15) << 2;       // 0..60
        *(float4*)&Qs[r * KSTRIDE + c] = *(const float4*)(qb + (size_t)(q0 + r) * DHD + c);
    }
    __syncthreads();

    // Q A-fragments, kept in registers for the whole kernel (Q pre-scaled by 1/8)
    uint32_t QA[8][4];
    #pragma unroll
    for (int kk = 0; kk < 8; kk++) {
        QA[kk][0] = f2tf(Qs[(wrow + g) * KSTRIDE + kk * 8 + tig]);
        QA[kk][1] = f2tf(Qs[(wrow + g + 8) * KSTRIDE + kk * 8 + tig]);
        QA[kk][2] = f2tf(Qs[(wrow + g) * KSTRIDE + kk * 8 + tig + 4]);
        QA[kk][3] = f2tf(Qs[(wrow + g + 8) * KSTRIDE + kk * 8 + tig + 4]);
    }

    float O[8][4];
    #pragma unroll
    for (int ni = 0; ni < 8; ni++)
        #pragma unroll
        for (int r = 0; r < 4; r++) O[ni][r] = 0.0f;

    float m0r = -1e30f, m1r = -1e30f;
    float l0 = 0.0f, l1 = 0.0f;
    float* Pw = Ps + warp * 16 * KSTRIDE;

    for (int kt = 0; kt < SS / 64; kt++) {
        __syncthreads();   // everyone done reading Ks/Vs from previous tile
        #pragma unroll
        for (int i = 0; i < 8; i++) {
            int idx = tid + i * 128;
            int r = idx >> 4;
            int c = (idx & 15) << 2;
            *(float4*)&Ks[r * KSTRIDE + c] =
                *(const float4*)(kb + (size_t)(kt * 64 + r) * DHD + c);
            *(float4*)&Vs[r * KSTRIDE + c] =
                *(const float4*)(vb + (size_t)(kt * 64 + r) * DHD + c);
        }
        __syncthreads();

        // S = Q @ K^T  (warp computes its 16 rows x 64 keys)
        float S[8][4];
        #pragma unroll
        for (int ni = 0; ni < 8; ni++)
            #pragma unroll
            for (int r = 0; r < 4; r++) S[ni][r] = 0.0f;

        #pragma unroll
        for (int kk = 0; kk < 8; kk++) {
            const int k8 = kk * 8;
            #pragma unroll
            for (int ni = 0; ni < 8; ni++) {
                uint32_t b0 = f2tf(Ks[(ni * 8 + g) * KSTRIDE + k8 + tig]);
                uint32_t b1 = f2tf(Ks[(ni * 8 + g) * KSTRIDE + k8 + tig + 4]);
                mma8(S[ni][0], S[ni][1], S[ni][2], S[ni][3],
                     QA[kk][0], QA[kk][1], QA[kk][2], QA[kk][3], b0, b1);
            }
        }

        // Online softmax: rows g (S[..][0..1]) and g+8 (S[..][2..3])
        float mt0 = -1e30f, mt1 = -1e30f;
        #pragma unroll
        for (int ni = 0; ni < 8; ni++) {
            mt0 = fmaxf(mt0, fmaxf(S[ni][0], S[ni][1]));
            mt1 = fmaxf(mt1, fmaxf(S[ni][2], S[ni][3]));
        }
        mt0 = fmaxf(mt0, __shfl_xor_sync(0xffffffffu, mt0, 1));
        mt0 = fmaxf(mt0, __shfl_xor_sync(0xffffffffu, mt0, 2));
        mt1 = fmaxf(mt1, __shfl_xor_sync(0xffffffffu, mt1, 1));
        mt1 = fmaxf(mt1, __shfl_xor_sync(0xffffffffu, mt1, 2));

        const float mn0 = fmaxf(m0r, mt0);
        const float mn1 = fmaxf(m1r, mt1);
        const float al0 = __expf(m0r - mn0);
        const float al1 = __expf(m1r - mn1);

        float rs0 = 0.0f, rs1 = 0.0f;
        #pragma unroll
        for (int ni = 0; ni < 8; ni++) {
            S[ni][0] = __expf(S[ni][0] - mn0);
            S[ni][1] = __expf(S[ni][1] - mn0);
            S[ni][2] = __expf(S[ni][2] - mn1);
            S[ni][3] = __expf(S[ni][3] - mn1);
            rs0 += S[ni][0] + S[ni][1];
            rs1 += S[ni][2] + S[ni][3];
        }
        rs0 += __shfl_xor_sync(0xffffffffu, rs0, 1);
        rs0 += __shfl_xor_sync(0xffffffffu, rs0, 2);
        rs1 += __shfl_xor_sync(0xffffffffu, rs1, 1);
        rs1 += __shfl_xor_sync(0xffffffffu, rs1, 2);

        l0 = l0 * al0 + rs0;
        l1 = l1 * al1 + rs1;
        m0r = mn0;
        m1r = mn1;

        #pragma unroll
        for (int ni = 0; ni < 8; ni++) {
            O[ni][0] *= al0; O[ni][1] *= al0;
            O[ni][2] *= al1; O[ni][3] *= al1;
        }

        // Stage P (tf32-rounded) to per-warp smem for C-frag -> A-frag relayout
        #pragma unroll
        for (int ni = 0; ni < 8; ni++) {
            float2 p0, p1;
            p0.x = __uint_as_float(f2tf(S[ni][0]));
            p0.y = __uint_as_float(f2tf(S[ni][1]));
            p1.x = __uint_as_float(f2tf(S[ni][2]));
            p1.y = __uint_as_float(f2tf(S[ni][3]));
            *(float2*)&Pw[g * KSTRIDE + ni * 8 + 2 * tig] = p0;
            *(float2*)&Pw[(g + 8) * KSTRIDE + ni * 8 + 2 * tig] = p1;
        }
        __syncwarp();

        // O += P @ V
        #pragma unroll
        for (int kk = 0; kk < 8; kk++) {
            const int k8 = kk * 8;
            uint32_t pa0 = __float_as_uint(Pw[g * KSTRIDE + k8 + tig]);
            uint32_t pa1 = __float_as_uint(Pw[(g + 8) * KSTRIDE + k8 + tig]);
            uint32_t pa2 = __float_as_uint(Pw[g * KSTRIDE + k8 + tig + 4]);
            uint32_t pa3 = __float_as_uint(Pw[(g + 8) * KSTRIDE + k8 + tig + 4]);
            #pragma unroll
            for (int ni = 0; ni < 8; ni++) {
                uint32_t b0 = f2tf(Vs[(k8 + tig) * KSTRIDE + ni * 8 + g]);
                uint32_t b1 = f2tf(Vs[(k8 + tig + 4) * KSTRIDE + ni * 8 + g]);
                mma8(O[ni][0], O[ni][1], O[ni][2], O[ni][3],
                     pa0, pa1, pa2, pa3, b0, b1);
            }
        }
        __syncwarp();  // all lanes done reading Pw before next tile overwrites it
    }

    // Normalize and write out: out[b][s][h*64+dh], [B,S,D] layout
    const float il0 = 1.0f / l0;
    const float il1 = 1.0f / l1;
    const int b = bh >> 4;
    const int h = bh & 15;
    #pragma unroll
    for (int ni = 0; ni < 8; ni++) {
        const int dh = ni * 8 + 2 * tig;
        {
            int s = q0 + wrow + g;
            float2 v; v.x = O[ni][0] * il0; v.y = O[ni][1] * il0;
            *(float2*)(out + ((size_t)(b * SS + s) * HH + h) * DHD + dh) = v;
        }
        {
            int s = q0 + wrow + g + 8;
            float2 v; v.x = O[ni][2] * il1; v.y = O[ni][3] * il1;
            *(float2*)(out + ((size_t)(b * SS + s) * HH + h) * DHD + dh) = v;
        }
    }
}

// ============================================================================
// Launch
// ============================================================================
extern "C" void kernel_launch(void* const* d_in, const int* in_sizes, int n_in,
                              void* d_out, int out_size)
{
    const float* x  = (const float*)d_in[0];
    const float* Wq = (const float*)d_in[1];
    const float* bq = (const float*)d_in[2];
    const float* Wk = (const float*)d_in[3];
    const float* bk = (const float*)d_in[4];
    const float* Wv = (const float*)d_in[5];
    const float* bv = (const float*)d_in[6];
    float* out = (float*)d_out;

    dim3 g1(64, 24);
    qkv_gemm_kernel<<<g1, 256>>>(x, Wq, bq, Wk, bk, Wv, bv);

    const int smem = (3 * 64 * KSTRIDE + 4 * 16 * KSTRIDE) * (int)sizeof(float); // 69632
    cudaFuncSetAttribute(attn_kernel, cudaFuncAttributeMaxDynamicSharedMemorySize, smem);
    dim3 g2(SS / 64, BB * HH);
    attn_kernel<<<g2, 128, smem>>>(out);
}

// round 5
// speedup vs baseline: 1.3453x; 1.3453x over previous
#include <cuda_runtime.h>
#include <cstdint>

#define BB 4
#define SS 2048
#define HH 16
#define DHD 64
#define DD 1024
#define MTOT (BB * SS)   // 8192

// Scratch. Q pre-scaled by 1/8; Q/K/V stored tf32-rounded in [B,H,S,DH].
__device__ float g_q[(size_t)BB * HH * SS * DHD];
__device__ float g_k[(size_t)BB * HH * SS * DHD];
__device__ float g_v[(size_t)BB * HH * SS * DHD];
// tf32-rounded copies of x and W
__device__ float g_xt[(size_t)MTOT * DD];
__device__ float g_wt[3][(size_t)DD * DD];

__device__ __forceinline__ uint32_t f2tf(float f) {
    uint32_t u;
    asm("cvt.rna.tf32.f32 %0, %1;" : "=r"(u) : "f"(f));
    return u;
}
__device__ __forceinline__ float f2tff(float f) { return __uint_as_float(f2tf(f)); }

__device__ __forceinline__ void mma8(float& d0, float& d1, float& d2, float& d3,
                                     uint32_t a0, uint32_t a1, uint32_t a2, uint32_t a3,
                                     uint32_t b0, uint32_t b1) {
    asm volatile(
        "mma.sync.aligned.m16n8k8.row.col.f32.tf32.tf32.f32 "
        "{%0,%1,%2,%3}, {%4,%5,%6,%7}, {%8,%9}, {%0,%1,%2,%3};"
        : "+f"(d0), "+f"(d1), "+f"(d2), "+f"(d3)
        : "r"(a0), "r"(a1), "r"(a2), "r"(a3), "r"(b0), "r"(b1));
}

__device__ __forceinline__ void cp16(void* smem, const void* gmem) {
    uint32_t s = (uint32_t)__cvta_generic_to_shared(smem);
    asm volatile("cp.async.cg.shared.global [%0], [%1], 16;" :: "r"(s), "l"(gmem));
}
#define CP_COMMIT() asm volatile("cp.async.commit_group;")
#define CP_WAIT(N)  asm volatile("cp.async.wait_group %0;" :: "n"(N))

// ============================================================================
// Kernel 0: round fp32 -> tf32-in-fp32 (one pass over x and each W)
// ============================================================================
__global__ __launch_bounds__(256) void cvt_tf32_kernel(const float4* __restrict__ src,
                                                       int which, int n4) {
    float4* dst = (which == 0) ? (float4*)g_xt : (float4*)g_wt[which - 1];
    int i = blockIdx.x * 256 + threadIdx.x;
    if (i < n4) {
        float4 v = src[i];
        v.x = f2tff(v.x); v.y = f2tff(v.y); v.z = f2tff(v.z); v.w = f2tff(v.w);
        dst[i] = v;
    }
}

// ============================================================================
// Kernel 1: fused QKV projection GEMM (tf32 mma, fp32 accum, cp.async 2-stage)
// 128x128 block tile, 4 warps, warp tile 64x64, k-step 32.
// grid = (64 m-tiles, 24 nt: 8 per matrix x {Q,K,V}), 128 threads.
// ============================================================================
#define XS_ST (128 * 36)   // floats per X stage
#define WS_ST (32 * 132)   // floats per W stage

__global__ __launch_bounds__(128) void qkv_gemm_kernel(
    const float* __restrict__ bq, const float* __restrict__ bk,
    const float* __restrict__ bv)
{
    extern __shared__ float sm[];
    float* Xs = sm;                 // 2 stages x 128x36
    float* Wsm = sm + 2 * XS_ST;    // 2 stages x 32x132

    const int mt = blockIdx.x;
    const int nt = blockIdx.y;
    const int mat = nt >> 3;
    const int n0 = (nt & 7) * 128;

    const float* W = g_wt[mat];
    const float* bias = (mat == 0) ? bq : (mat == 1) ? bk : bv;
    float* outp = (mat == 0) ? g_q : (mat == 1) ? g_k : g_v;
    const float scale = (mat == 0) ? 0.125f : 1.0f;

    const int tid  = threadIdx.x;
    const int warp = tid >> 5;
    const int lane = tid & 31;
    const int g    = lane >> 2;
    const int tig  = lane & 3;
    const int wm   = (warp & 1) * 64;
    const int wn   = (warp >> 1) * 64;
    const int m0   = mt * 128;

    const float* xb = g_xt + (size_t)m0 * DD;

    float acc[4][8][4];
    #pragma unroll
    for (int mi = 0; mi < 4; mi++)
        #pragma unroll
        for (int ni = 0; ni < 8; ni++)
            #pragma unroll
            for (int r = 0; r < 4; r++) acc[mi][ni][r] = 0.0f;

    // stage loader
    auto load_stage = [&](int t, int st) {
        const int k0 = t * 32;
        float* Xst = Xs + st * XS_ST;
        float* Wst = Wsm + st * WS_ST;
        #pragma unroll
        for (int i = 0; i < 8; i++) {
            int idx = tid + i * 128;
            int r = idx >> 3, c = (idx & 7) << 2;     // X 128x32
            cp16(&Xst[r * 36 + c], xb + (size_t)r * DD + k0 + c);
        }
        #pragma unroll
        for (int i = 0; i < 8; i++) {
            int idx = tid + i * 128;
            int r = idx >> 5, c = (idx & 31) << 2;    // W 32x128
            cp16(&Wst[r * 132 + c], W + (size_t)(k0 + r) * DD + n0 + c);
        }
        CP_COMMIT();
    };

    load_stage(0, 0);

    const int NT = DD / 32;   // 32
    for (int t = 0; t < NT; t++) {
        if (t + 1 < NT) { load_stage(t + 1, (t + 1) & 1); CP_WAIT(1); }
        else            { CP_WAIT(0); }
        __syncthreads();

        const float* Xst = Xs + (t & 1) * XS_ST;
        const float* Wst = Wsm + (t & 1) * WS_ST;
        #pragma unroll
        for (int kk = 0; kk < 4; kk++) {
            const int k8 = kk * 8;
            uint32_t A[4][4];
            #pragma unroll
            for (int mi = 0; mi < 4; mi++) {
                const int row = wm + mi * 16;
                A[mi][0] = __float_as_uint(Xst[(row + g) * 36 + k8 + tig]);
                A[mi][1] = __float_as_uint(Xst[(row + g + 8) * 36 + k8 + tig]);
                A[mi][2] = __float_as_uint(Xst[(row + g) * 36 + k8 + tig + 4]);
                A[mi][3] = __float_as_uint(Xst[(row + g + 8) * 36 + k8 + tig + 4]);
            }
            #pragma unroll
            for (int ni = 0; ni < 8; ni++) {
                const int col = wn + ni * 8 + g;
                uint32_t b0 = __float_as_uint(Wst[(k8 + tig) * 132 + col]);
                uint32_t b1 = __float_as_uint(Wst[(k8 + tig + 4) * 132 + col]);
                #pragma unroll
                for (int mi = 0; mi < 4; mi++)
                    mma8(acc[mi][ni][0], acc[mi][ni][1], acc[mi][ni][2], acc[mi][ni][3],
                         A[mi][0], A[mi][1], A[mi][2], A[mi][3], b0, b1);
            }
        }
        __syncthreads();
    }

    // Epilogue: bias, scale, tf32-round, scatter to [B,H,S,DH]
    #pragma unroll
    for (int mi = 0; mi < 4; mi++) {
        #pragma unroll
        for (int ni = 0; ni < 8; ni++) {
            const int n = n0 + wn + ni * 8 + 2 * tig;
            const int h = n >> 6;
            const int dh = n & 63;
            const float bv0 = bias[n];
            const float bv1 = bias[n + 1];
            const int mbase = m0 + wm + mi * 16;
            {
                int m = mbase + g;
                int b = m >> 11, s = m & 2047;
                float2 v;
                v.x = f2tff((acc[mi][ni][0] + bv0) * scale);
                v.y = f2tff((acc[mi][ni][1] + bv1) * scale);
                *(float2*)(outp + ((size_t)(b * HH + h) * SS + s) * DHD + dh) = v;
            }
            {
                int m = mbase + g + 8;
                int b = m >> 11, s = m & 2047;
                float2 v;
                v.x = f2tff((acc[mi][ni][2] + bv0) * scale);
                v.y = f2tff((acc[mi][ni][3] + bv1) * scale);
                *(float2*)(outp + ((size_t)(b * HH + h) * SS + s) * DHD + dh) = v;
            }
        }
    }
}

// ============================================================================
// Kernel 2: flash attention (tf32 mma, online softmax)
// grid = (16 q-tiles of 128, 64 bh), 128 threads (4 warps x 32 q-rows).
// K/V tiles of 32 keys, cp.async double-buffered. Inputs pre-tf32-rounded.
// ============================================================================
#define KST 68             // K/V smem row stride (floats)
#define PST 36             // P smem row stride
#define KV_ST (32 * KST)   // floats per K or V stage
#define QP_FLOATS (128 * KST)

__global__ __launch_bounds__(128, 2) void attn_kernel(float* __restrict__ out)
{
    extern __shared__ float sm[];
    float* QP = sm;                       // Q (128xKST), later reused as P
    float* Ks = sm + QP_FLOATS;           // 2 x 32xKST
    float* Vs = Ks + 2 * KV_ST;           // 2 x 32xKST

    const int bh = blockIdx.y;
    const int q0 = blockIdx.x * 128;

    const float* qb = g_q + (size_t)bh * SS * DHD + (size_t)q0 * DHD;
    const float* kb = g_k + (size_t)bh * SS * DHD;
    const float* vb = g_v + (size_t)bh * SS * DHD;

    const int tid  = threadIdx.x;
    const int warp = tid >> 5;
    const int lane = tid & 31;
    const int g    = lane >> 2;
    const int tig  = lane & 3;

    // Load Q tile 128x64 to smem
    #pragma unroll
    for (int i = 0; i < 16; i++) {
        int idx = tid + i * 128;
        int r = idx >> 4, c = (idx & 15) << 2;
        *(float4*)&QP[r * KST + c] = *(const float4*)(qb + (size_t)r * DHD + c);
    }
    __syncthreads();

    // Q A-fragments in registers: 2 m-tiles of 16 rows per warp
    uint32_t QA[8][2][4];
    #pragma unroll
    for (int kk = 0; kk < 8; kk++) {
        #pragma unroll
        for (int mi = 0; mi < 2; mi++) {
            const int qrow = warp * 32 + mi * 16;
            QA[kk][mi][0] = __float_as_uint(QP[(qrow + g) * KST + kk * 8 + tig]);
            QA[kk][mi][1] = __float_as_uint(QP[(qrow + g + 8) * KST + kk * 8 + tig]);
            QA[kk][mi][2] = __float_as_uint(QP[(qrow + g) * KST + kk * 8 + tig + 4]);
            QA[kk][mi][3] = __float_as_uint(QP[(qrow + g + 8) * KST + kk * 8 + tig + 4]);
        }
    }

    float O[2][8][4];
    #pragma unroll
    for (int mi = 0; mi < 2; mi++)
        #pragma unroll
        for (int ni = 0; ni < 8; ni++)
            #pragma unroll
            for (int r = 0; r < 4; r++) O[mi][ni][r] = 0.0f;

    float mrun[2][2], lrun[2][2];
    #pragma unroll
    for (int mi = 0; mi < 2; mi++) {
        mrun[mi][0] = -1e30f; mrun[mi][1] = -1e30f;
        lrun[mi][0] = 0.0f;   lrun[mi][1] = 0.0f;
    }

    float* Pw = QP + warp * (32 * PST);   // per-warp 32x36 P region (overlaps Q)

    auto load_kv = [&](int t, int st) {
        #pragma unroll
        for (int i = 0; i < 4; i++) {
            int idx = tid + i * 128;
            int r = idx >> 4, c = (idx & 15) << 2;
            cp16(&Ks[st * KV_ST + r * KST + c], kb + (size_t)(t * 32 + r) * DHD + c);
        }
        #pragma unroll
        for (int i = 0; i < 4; i++) {
            int idx = tid + i * 128;
            int r = idx >> 4, c = (idx & 15) << 2;
            cp16(&Vs[st * KV_ST + r * KST + c], vb + (size_t)(t * 32 + r) * DHD + c);
        }
        CP_COMMIT();
    };

    load_kv(0, 0);

    const int NT = SS / 32;   // 64
    for (int t = 0; t < NT; t++) {
        if (t + 1 < NT) { load_kv(t + 1, (t + 1) & 1); CP_WAIT(1); }
        else            { CP_WAIT(0); }
        __syncthreads();

        const float* Kst = Ks + (t & 1) * KV_ST;
        const float* Vst = Vs + (t & 1) * KV_ST;

        // S = Q @ K^T : per warp 32 rows x 32 keys
        float S[2][4][4];
        #pragma unroll
        for (int mi = 0; mi < 2; mi++)
            #pragma unroll
            for (int ni = 0; ni < 4; ni++)
                #pragma unroll
                for (int r = 0; r < 4; r++) S[mi][ni][r] = 0.0f;

        #pragma unroll
        for (int kk = 0; kk < 8; kk++) {
            const int k8 = kk * 8;
            #pragma unroll
            for (int ni = 0; ni < 4; ni++) {
                uint32_t b0 = __float_as_uint(Kst[(ni * 8 + g) * KST + k8 + tig]);
                uint32_t b1 = __float_as_uint(Kst[(ni * 8 + g) * KST + k8 + tig + 4]);
                #pragma unroll
                for (int mi = 0; mi < 2; mi++)
                    mma8(S[mi][ni][0], S[mi][ni][1], S[mi][ni][2], S[mi][ni][3],
                         QA[kk][mi][0], QA[kk][mi][1], QA[kk][mi][2], QA[kk][mi][3],
                         b0, b1);
            }
        }

        // Online softmax per mi (row pairs g, g+8)
        #pragma unroll
        for (int mi = 0; mi < 2; mi++) {
            float mt0 = -1e30f, mt1 = -1e30f;
            #pragma unroll
            for (int ni = 0; ni < 4; ni++) {
                mt0 = fmaxf(mt0, fmaxf(S[mi][ni][0], S[mi][ni][1]));
                mt1 = fmaxf(mt1, fmaxf(S[mi][ni][2], S[mi][ni][3]));
            }
            mt0 = fmaxf(mt0, __shfl_xor_sync(0xffffffffu, mt0, 1));
            mt0 = fmaxf(mt0, __shfl_xor_sync(0xffffffffu, mt0, 2));
            mt1 = fmaxf(mt1, __shfl_xor_sync(0xffffffffu, mt1, 1));
            mt1 = fmaxf(mt1, __shfl_xor_sync(0xffffffffu, mt1, 2));

            const float mn0 = fmaxf(mrun[mi][0], mt0);
            const float mn1 = fmaxf(mrun[mi][1], mt1);
            const float al0 = __expf(mrun[mi][0] - mn0);
            const float al1 = __expf(mrun[mi][1] - mn1);

            float rs0 = 0.0f, rs1 = 0.0f;
            #pragma unroll
            for (int ni = 0; ni < 4; ni++) {
                S[mi][ni][0] = __expf(S[mi][ni][0] - mn0);
                S[mi][ni][1] = __expf(S[mi][ni][1] - mn0);
                S[mi][ni][2] = __expf(S[mi][ni][2] - mn1);
                S[mi][ni][3] = __expf(S[mi][ni][3] - mn1);
                rs0 += S[mi][ni][0] + S[mi][ni][1];
                rs1 += S[mi][ni][2] + S[mi][ni][3];
            }
            rs0 += __shfl_xor_sync(0xffffffffu, rs0, 1);
            rs0 += __shfl_xor_sync(0xffffffffu, rs0, 2);
            rs1 += __shfl_xor_sync(0xffffffffu, rs1, 1);
            rs1 += __shfl_xor_sync(0xffffffffu, rs1, 2);

            lrun[mi][0] = lrun[mi][0] * al0 + rs0;
            lrun[mi][1] = lrun[mi][1] * al1 + rs1;
            mrun[mi][0] = mn0;
            mrun[mi][1] = mn1;

            // rescale O (skip when running max unchanged: al == 1 exactly)
            if (!__all_sync(0xffffffffu, (al0 == 1.0f) & (al1 == 1.0f))) {
                #pragma unroll
                for (int ni = 0; ni < 8; ni++) {
                    O[mi][ni][0] *= al0; O[mi][ni][1] *= al0;
                    O[mi][ni][2] *= al1; O[mi][ni][3] *= al1;
                }
            }
        }

        // Stage P (tf32-rounded) to per-warp smem for C->A relayout
        #pragma unroll
        for (int mi = 0; mi < 2; mi++) {
            #pragma unroll
            for (int ni = 0; ni < 4; ni++) {
                const int base = (mi * 16 + g) * PST + ni * 8 + 2 * tig;
                float2 p0, p1;
                p0.x = f2tff(S[mi][ni][0]); p0.y = f2tff(S[mi][ni][1]);
                p1.x = f2tff(S[mi][ni][2]); p1.y = f2tff(S[mi][ni][3]);
                *(float2*)&Pw[base] = p0;
                *(float2*)&Pw[base + 8 * PST] = p1;
            }
        }
        __syncwarp();

        // O += P @ V
        #pragma unroll
        for (int kk = 0; kk < 4; kk++) {
            const int k8 = kk * 8;
            uint32_t pa[2][4];
            #pragma unroll
            for (int mi = 0; mi < 2; mi++) {
                const int base = (mi * 16 + g) * PST;
                pa[mi][0] = __float_as_uint(Pw[base + k8 + tig]);
                pa[mi][1] = __float_as_uint(Pw[base + 8 * PST + k8 + tig]);
                pa[mi][2] = __float_as_uint(Pw[base + k8 + tig + 4]);
                pa[mi][3] = __float_as_uint(Pw[base + 8 * PST + k8 + tig + 4]);
            }
            #pragma unroll
            for (int ni = 0; ni < 8; ni++) {
                uint32_t b0 = __float_as_uint(Vst[(k8 + tig) * KST + ni * 8 + g]);
                uint32_t b1 = __float_as_uint(Vst[(k8 + tig + 4) * KST + ni * 8 + g]);
                #pragma unroll
                for (int mi = 0; mi < 2; mi++)
                    mma8(O[mi][ni][0], O[mi][ni][1], O[mi][ni][2], O[mi][ni][3],
                         pa[mi][0], pa[mi][1], pa[mi][2], pa[mi][3], b0, b1);
            }
        }
        __syncwarp();
        __syncthreads();   // all warps done with this K/V stage before reload
    }

    // Normalize + write [B,S,H*DH]
    const int b = bh >> 4;
    const int h = bh & 15;
    #pragma unroll
    for (int mi = 0; mi < 2; mi++) {
        const float il0 = 1.0f / lrun[mi][0];
        const float il1 = 1.0f / lrun[mi][1];
        #pragma unroll
        for (int ni = 0; ni < 8; ni++) {
            const int dh = ni * 8 + 2 * tig;
            {
                int s = q0 + warp * 32 + mi * 16 + g;
                float2 v; v.x = O[mi][ni][0] * il0; v.y = O[mi][ni][1] * il0;
                *(float2*)(out + ((size_t)(b * SS + s) * HH + h) * DHD + dh) = v;
            }
            {
                int s = q0 + warp * 32 + mi * 16 + g + 8;
                float2 v; v.x = O[mi][ni][2] * il1; v.y = O[mi][ni][3] * il1;
                *(float2*)(out + ((size_t)(b * SS + s) * HH + h) * DHD + dh) = v;
            }
        }
    }
}

// ============================================================================
// Launch
// ============================================================================
extern "C" void kernel_launch(void* const* d_in, const int* in_sizes, int n_in,
                              void* d_out, int out_size)
{
    const float* x  = (const float*)d_in[0];
    const float* Wq = (const float*)d_in[1];
    const float* bq = (const float*)d_in[2];
    const float* Wk = (const float*)d_in[3];
    const float* bk = (const float*)d_in[4];
    const float* Wv = (const float*)d_in[5];
    const float* bv = (const float*)d_in[6];
    float* out = (float*)d_out;

    // Prep: tf32-round x and W
    {
        int n4x = MTOT * DD / 4;
        int n4w = DD * DD / 4;
        cvt_tf32_kernel<<<(n4x + 255) / 256, 256>>>((const float4*)x, 0, n4x);
        cvt_tf32_kernel<<<(n4w + 255) / 256, 256>>>((const float4*)Wq, 1, n4w);
        cvt_tf32_kernel<<<(n4w + 255) / 256, 256>>>((const float4*)Wk, 2, n4w);
        cvt_tf32_kernel<<<(n4w + 255) / 256, 256>>>((const float4*)Wv, 3, n4w);
    }

    // QKV GEMM
    {
        const int smem = (2 * XS_ST + 2 * WS_ST) * (int)sizeof(float);   // 70656
        cudaFuncSetAttribute(qkv_gemm_kernel,
                             cudaFuncAttributeMaxDynamicSharedMemorySize, smem);
        dim3 grd(MTOT / 128, 24);
        qkv_gemm_kernel<<<grd, 128, smem>>>(bq, bk, bv);
    }

    // Attention
    {
        const int smem = (QP_FLOATS + 4 * KV_ST) * (int)sizeof(float);   // 69632
        cudaFuncSetAttribute(attn_kernel,
                             cudaFuncAttributeMaxDynamicSharedMemorySize, smem);
        dim3 grd(SS / 128, BB * HH);
        attn_kernel<<<grd, 128, smem>>>(out);
    }
}